// round 15
// baseline (speedup 1.0000x reference)
#include <cuda_runtime.h>
#include <cuda_fp16.h>
#include <cstdint>
#include <cstddef>

// ---------------- problem constants ----------------
constexpr int E    = 4;
constexpr int Bn   = 32;
constexpr int CIN  = 64;
constexpr int H    = 64;
constexpr int W    = 64;
constexpr int COUT = 128;
constexpr int HO   = 62;
constexpr int WO   = 62;
constexpr int NTAPS = 9;

// ---------------- SMEM layout (byte offsets) ----------------
// G: transposed features [264 pos][64 ch] fp16, 128B rows, XOR-16B swizzle
constexpr int SM_G     = 0;            // 33792 B
// Weights: THREE buffers (fp16, 144B row pitch), 18432 B each
constexpr int SM_W     = 33792;        // 3 x 18432 = 55296 B -> end 89088
// stage fp32 chunk (32 ch x 257 words = 32896 B) unions with W0+W1 (prologue only)
constexpr int SM_STAGE = 33792;
constexpr int SM_BIAS  = 89088;        // 512 B
constexpr int SM_TOTAL = 89600;        // x2 blocks = 179200 <= 228KB

constexpr int WBLK = 18432;            // bytes per (e,tap), 144B pitch

// ---------------- prepped weights (fp16, 144B pitch) ----------------
__device__ __align__(16) unsigned char g_wprep[E * NTAPS * WBLK];

__global__ void prep_weights_kernel(const float* __restrict__ wgt) {
    int idx = blockIdx.x * blockDim.x + threadIdx.x;
    if (idx >= E * NTAPS * COUT * CIN) return;
    int i    = idx & 63;          // input channel (k index)
    int j    = (idx >> 6) & 127;  // cout (m index)
    int rest = idx >> 13;
    int tap  = rest % NTAPS;
    int e    = rest / NTAPS;

    float v = wgt[(((size_t)e * CIN + i) * COUT + j) * 9 + tap];
    size_t base = (size_t)(e * NTAPS + tap) * WBLK;
    *(__half*)(g_wprep + base + (size_t)j * 144 + i * 2) = __float2half(v);
}

// ---------------- PTX helpers (plain sm_80-class) ----------------
__device__ __forceinline__ uint32_t smem_u32(const void* p) {
    uint32_t a;
    asm("{ .reg .u64 t; cvta.to.shared.u64 t, %1; cvt.u32.u64 %0, t; }" : "=r"(a) : "l"(p));
    return a;
}
__device__ __forceinline__ void cpasync16(uint32_t dst, const void* src) {
    asm volatile("cp.async.cg.shared.global [%0], [%1], 16;" :: "r"(dst), "l"(src));
}
__device__ __forceinline__ void cpasync_commit() {
    asm volatile("cp.async.commit_group;" ::: "memory");
}
__device__ __forceinline__ void cpasync_wait1() {
    asm volatile("cp.async.wait_group 1;" ::: "memory");
}
__device__ __forceinline__ void ldsm_x4(uint32_t& r0, uint32_t& r1, uint32_t& r2, uint32_t& r3,
                                        uint32_t addr) {
    asm volatile("ldmatrix.sync.aligned.m8n8.x4.shared.b16 {%0,%1,%2,%3}, [%4];"
                 : "=r"(r0), "=r"(r1), "=r"(r2), "=r"(r3) : "r"(addr));
}
__device__ __forceinline__ void mma16816(float* c, const uint32_t* a, uint32_t b0, uint32_t b1) {
    asm volatile(
        "mma.sync.aligned.m16n8k16.row.col.f32.f16.f16.f32 "
        "{%0,%1,%2,%3}, {%4,%5,%6,%7}, {%8,%9}, {%0,%1,%2,%3};"
        : "+f"(c[0]), "+f"(c[1]), "+f"(c[2]), "+f"(c[3])
        : "r"(a[0]), "r"(a[1]), "r"(a[2]), "r"(a[3]), "r"(b0), "r"(b1));
}

// ---------------- main kernel ----------------
// 256 threads (8 warps). jbase=(wid&1)*64 (couts), pbase=(wid>>1)*32 (pos).
// Per warp: 4 m16 x 4 n8 tiles; K=576 = 9 taps x 4 k16; single fp16 term.
// Weight buffers: buf(t) = (t+2)%3. Prefetch for tap t+2 issued at top of tap t
// into (t+1)%3 = buffer freed by tap t-1 (fenced by this tap's barrier).
__global__ __launch_bounds__(256, 2)
void conv_hmma_kernel(const float* __restrict__ feat,
                      const float* __restrict__ bias,
                      float* __restrict__ out)
{
    extern __shared__ __align__(128) char smem[];
    const int tid  = threadIdx.x;
    const int wid  = tid >> 5;
    const int lane = tid & 31;
    const int eb   = blockIdx.y;
    const int e    = eb >> 5;
    const int y0   = blockIdx.x * 2;
    const uint32_t sb = smem_u32(smem);

    const unsigned char* wsrc = g_wprep + (size_t)(e * NTAPS) * WBLK;

    // --- 0) prefetch tap-0 weights into buf2 (disjoint from stage region) ---
    {
        const unsigned char* s0 = wsrc;               // tap 0
        uint32_t dst = sb + SM_W + 2 * WBLK;
#pragma unroll
        for (int c = 0; c < 5; c++) {
            int chunk = c * 256 + tid;
            if (chunk < 1152) cpasync16(dst + chunk * 16, s0 + chunk * 16);
        }
        cpasync_commit();    // group g0 (tap 0)
    }

    // zero G pad rows (pos 256..263), load bias
    if (tid < 128) {
        ((uint2*)(smem + SM_G + 256 * 128))[tid] = make_uint2(0u, 0u);
        ((float*)(smem + SM_BIAS))[tid] = bias[e * COUT + tid];
    }

    // --- 1) stage fp32 (vectorized) + build G (fp16) in two 32-channel chunks ---
    const float* fb = feat + (size_t)eb * CIN * H * W + (size_t)y0 * W;
    float* sf = (float*)(smem + SM_STAGE);
#pragma unroll
    for (int q = 0; q < 2; q++) {
        __syncthreads();
        // 32 ch x 256 floats = 2048 float4; 8 per thread, coalesced LDG.128
#pragma unroll
        for (int c = 0; c < 8; c++) {
            int f4idx = c * 256 + tid;
            int i   = f4idx >> 6;
            int rx4 = f4idx & 63;
            float4 v = *(const float4*)(fb + (size_t)(q * 32 + i) * (H * W) + rx4 * 4);
            float* d = sf + i * 257 + rx4 * 4;
            d[0] = v.x; d[1] = v.y; d[2] = v.z; d[3] = v.w;
        }
        __syncthreads();
        const int ch    = q * 32 + lane;
        const int chnk  = (ch * 2) >> 4;
        const int cin16 = (ch * 2) & 15;
#pragma unroll
        for (int it = 0; it < 32; it++) {
            const int p = wid * 32 + it;
            float v = sf[lane * 257 + p];
            uint32_t boff = (uint32_t)p * 128 + (uint32_t)((chnk ^ (p & 7)) << 4) + cin16;
            *(__half*)(smem + SM_G + boff) = __float2half(v);
        }
    }
    __syncthreads();   // stage dead: W0/W1 region free

    // --- 2) prefetch tap-1 weights into buf0 ---
    {
        const unsigned char* s1 = wsrc + WBLK;        // tap 1
        uint32_t dst = sb + SM_W;                     // buf0
#pragma unroll
        for (int c = 0; c < 5; c++) {
            int chunk = c * 256 + tid;
            if (chunk < 1152) cpasync16(dst + chunk * 16, s1 + chunk * 16);
        }
        cpasync_commit();    // group g1 (tap 1)
    }

    // --- 3) main loop over 9 taps: ONE barrier per tap ---
    const int jbase = (wid & 1) * 64;
    const int pbase = (wid >> 1) * 32;
    const int tt = lane >> 3, r = lane & 7;
    const uint32_t aoff = (uint32_t)(((tt & 1) * 8 + r) * 144 + (tt >> 1) * 16);
    const int br  = (tt >> 1) * 8 + r;
    const int kcb = tt & 1;

    float acc[4][4][4];
#pragma unroll
    for (int a = 0; a < 4; a++)
#pragma unroll
        for (int b = 0; b < 4; b++)
#pragma unroll
            for (int c = 0; c < 4; c++) acc[a][b][c] = 0.0f;

    for (int t = 0; t < NTAPS; t++) {
        // my group for tap t is done when <=1 younger group pends
        cpasync_wait1();
        __syncthreads();   // visibility of everyone's tap-t copies + frees buf of tap t-1

        // prefetch tap t+2 into the buffer tap t-1 just released ((t+1)%3)
        if (t + 2 < NTAPS) {
            const unsigned char* src = wsrc + (size_t)(t + 2) * WBLK;
            uint32_t dst = sb + SM_W + ((t + 1) % 3) * WBLK;
#pragma unroll
            for (int c = 0; c < 5; c++) {
                int chunk = c * 256 + tid;
                if (chunk < 1152) cpasync16(dst + chunk * 16, src + chunk * 16);
            }
        }
        cpasync_commit();   // always commit (possibly empty) to keep numbering

        const uint32_t whi = sb + SM_W + ((t + 2) % 3) * WBLK;
        const int ky = t / 3, kx = t - ky * 3;
        const int pshift = pbase + ky * 64 + kx;

#pragma unroll
        for (int kq = 0; kq < 4; kq++) {
            const int k0 = kq * 16;
            uint32_t ah[4][4];
#pragma unroll
            for (int mt = 0; mt < 4; mt++) {
                uint32_t abase = (uint32_t)((jbase + mt * 16) * 144 + k0 * 2) + aoff;
                ldsm_x4(ah[mt][0], ah[mt][1], ah[mt][2], ah[mt][3], whi + abase);
            }
#pragma unroll
            for (int nt = 0; nt < 2; nt++) {
                const int P  = pshift + nt * 16 + br;
                const int kc = (k0 >> 3) + kcb;
                const uint32_t gb = (uint32_t)P * 128 + (uint32_t)((kc ^ (P & 7)) << 4);
                uint32_t bh[4];
                ldsm_x4(bh[0], bh[1], bh[2], bh[3], sb + SM_G + gb);
#pragma unroll
                for (int mt = 0; mt < 4; mt++) {
#pragma unroll
                    for (int sub = 0; sub < 2; sub++) {
                        mma16816(acc[mt][nt * 2 + sub], ah[mt],
                                 bh[2 * sub], bh[2 * sub + 1]);
                    }
                }
            }
        }
    }

    // --- 4) epilogue: bias + float2 stores ---
    const float* sbias = (const float*)(smem + SM_BIAS);
#pragma unroll
    for (int mt = 0; mt < 4; mt++) {
        const int j0 = jbase + mt * 16 + (lane >> 2);
        const float b0 = sbias[j0];
        const float b1 = sbias[j0 + 8];
#pragma unroll
        for (int q = 0; q < 4; q++) {
            const int pos = pbase + q * 8 + 2 * (lane & 3);
            const int x = pos & 63;
            const int y = y0 + (pos >> 6);
            if (x < WO) {
                float2 v0 = make_float2(acc[mt][q][0] + b0, acc[mt][q][1] + b0);
                float2 v1 = make_float2(acc[mt][q][2] + b1, acc[mt][q][3] + b1);
                *(float2*)(out + (((size_t)eb * COUT + j0)     * HO + y) * WO + x) = v0;
                *(float2*)(out + (((size_t)eb * COUT + j0 + 8) * HO + y) * WO + x) = v1;
            }
        }
    }
}

// ---------------- launch ----------------
extern "C" void kernel_launch(void* const* d_in, const int* in_sizes, int n_in,
                              void* d_out, int out_size)
{
    const float* feat = (const float*)d_in[0];  // (E, B, C_in, H, W)
    const float* wgt  = (const float*)d_in[1];  // (E, C_in, C_out, 3, 3)
    const float* bias = (const float*)d_in[2];  // (E, C_out)
    float*       out  = (float*)d_out;          // (E, B, C_out, 62, 62)

    cudaFuncSetAttribute(conv_hmma_kernel,
                         cudaFuncAttributeMaxDynamicSharedMemorySize, SM_TOTAL);

    const int total = E * NTAPS * COUT * CIN;
    prep_weights_kernel<<<(total + 255) / 256, 256>>>(wgt);

    dim3 grid(HO / 2, E * Bn);  // (31, 128)
    conv_hmma_kernel<<<grid, 256, SM_TOTAL>>>(feat, bias, out);
}

// round 16
// speedup vs baseline: 1.1603x; 1.1603x over previous
#include <cuda_runtime.h>
#include <cuda_fp16.h>
#include <cstdint>
#include <cstddef>

// ---------------- problem constants ----------------
constexpr int E    = 4;
constexpr int Bn   = 32;
constexpr int CIN  = 64;
constexpr int H    = 64;
constexpr int W    = 64;
constexpr int COUT = 128;
constexpr int HO   = 62;
constexpr int WO   = 62;
constexpr int NTAPS = 9;

// ---------------- SMEM layout (byte offsets) ----------------
// G: transposed features [264 pos][64 ch] fp16, 128B rows, XOR-16B swizzle
constexpr int SM_G     = 0;          // 33792 B
// Weight buffers (fp16, 144B row pitch): 18432 B each, double-buffered
constexpr int SM_W0    = 33792;
constexpr int SM_W1    = 52224;
constexpr int SM_BIAS  = 70656;      // 512 B
constexpr int SM_TOTAL = 71168;      // x2 blocks = 142336 <= 228KB

constexpr int WBLK = 18432;          // bytes per (e,tap), 144B pitch

// ---------------- prepped weights (fp16, 144B pitch) ----------------
__device__ __align__(16) unsigned char g_wprep[E * NTAPS * WBLK];

__global__ void prep_weights_kernel(const float* __restrict__ wgt) {
    int idx = blockIdx.x * blockDim.x + threadIdx.x;
    if (idx >= E * NTAPS * COUT * CIN) return;
    int i    = idx & 63;          // input channel (k index)
    int j    = (idx >> 6) & 127;  // cout (m index)
    int rest = idx >> 13;
    int tap  = rest % NTAPS;
    int e    = rest / NTAPS;

    float v = wgt[(((size_t)e * CIN + i) * COUT + j) * 9 + tap];
    size_t base = (size_t)(e * NTAPS + tap) * WBLK;
    *(__half*)(g_wprep + base + (size_t)j * 144 + i * 2) = __float2half(v);
}

// ---------------- PTX helpers (plain sm_80-class) ----------------
__device__ __forceinline__ uint32_t smem_u32(const void* p) {
    uint32_t a;
    asm("{ .reg .u64 t; cvta.to.shared.u64 t, %1; cvt.u32.u64 %0, t; }" : "=r"(a) : "l"(p));
    return a;
}
__device__ __forceinline__ void cpasync16(uint32_t dst, const void* src) {
    asm volatile("cp.async.cg.shared.global [%0], [%1], 16;" :: "r"(dst), "l"(src));
}
__device__ __forceinline__ void cpasync_commit() {
    asm volatile("cp.async.commit_group;" ::: "memory");
}
__device__ __forceinline__ void cpasync_wait0() {
    asm volatile("cp.async.wait_group 0;" ::: "memory");
}
__device__ __forceinline__ void cpasync_wait1() {
    asm volatile("cp.async.wait_group 1;" ::: "memory");
}
__device__ __forceinline__ void ldsm_x4(uint32_t& r0, uint32_t& r1, uint32_t& r2, uint32_t& r3,
                                        uint32_t addr) {
    asm volatile("ldmatrix.sync.aligned.m8n8.x4.shared.b16 {%0,%1,%2,%3}, [%4];"
                 : "=r"(r0), "=r"(r1), "=r"(r2), "=r"(r3) : "r"(addr));
}
__device__ __forceinline__ void mma16816(float* c, const uint32_t* a, uint32_t b0, uint32_t b1) {
    asm volatile(
        "mma.sync.aligned.m16n8k16.row.col.f32.f16.f16.f32 "
        "{%0,%1,%2,%3}, {%4,%5,%6,%7}, {%8,%9}, {%0,%1,%2,%3};"
        : "+f"(c[0]), "+f"(c[1]), "+f"(c[2]), "+f"(c[3])
        : "r"(a[0]), "r"(a[1]), "r"(a[2]), "r"(a[3]), "r"(b0), "r"(b1));
}

// ---------------- main kernel ----------------
// 256 threads (8 warps). jbase=(wid&1)*64 (couts), pbase=(wid>>1)*32 (pos).
// Per warp: 4 m16 x 4 n8 tiles; K=576 = 9 taps x 4 k16; single fp16 term.
__global__ __launch_bounds__(256, 2)
void conv_hmma_kernel(const float* __restrict__ feat,
                      const float* __restrict__ bias,
                      float* __restrict__ out)
{
    extern __shared__ __align__(128) char smem[];
    const int tid  = threadIdx.x;
    const int wid  = tid >> 5;
    const int lane = tid & 31;
    const int eb   = blockIdx.y;
    const int e    = eb >> 5;
    const int y0   = blockIdx.x * 2;
    const uint32_t sb = smem_u32(smem);

    const unsigned char* wsrc = g_wprep + (size_t)(e * NTAPS) * WBLK;

    // --- 0) prefetch tap-0 weights into W0 and tap-1 into W1 (no stage union now) ---
    {
#pragma unroll
        for (int c = 0; c < 5; c++) {
            int chunk = c * 256 + tid;
            if (chunk < 1152) cpasync16(sb + SM_W0 + chunk * 16, wsrc + chunk * 16);
        }
        cpasync_commit();
#pragma unroll
        for (int c = 0; c < 5; c++) {
            int chunk = c * 256 + tid;
            if (chunk < 1152) cpasync16(sb + SM_W1 + chunk * 16, wsrc + WBLK + chunk * 16);
        }
        cpasync_commit();
    }

    // --- 1) zero G pad rows (pos 256..263), load bias ---
    if (tid < 128) {
        ((uint2*)(smem + SM_G + 256 * 128))[tid] = make_uint2(0u, 0u);
        ((float*)(smem + SM_BIAS))[tid] = bias[e * COUT + tid];
    }

    // --- 2) build G directly: thread owns pos p = tid, loops 32 channel pairs ---
    // fb + ch*HW + p is contiguous over p for the 4 staged rows (y0..y0+3).
    {
        const float* fb = feat + (size_t)eb * CIN * H * W + (size_t)y0 * W;
        const int p   = tid;
        const int pxo = (p & 7);                       // XOR swizzle source bits
        char* grow = smem + SM_G + (size_t)p * 128;
#pragma unroll
        for (int cc = 0; cc < 32; cc++) {
            const int c0 = 2 * cc;                     // channels c0, c0+1
            float v0 = fb[(size_t)c0 * (H * W) + p];
            float v1 = fb[(size_t)(c0 + 1) * (H * W) + p];
            __half2 hp = __floats2half2_rn(v0, v1);
            const int chnk  = cc >> 2;                 // (c0*2)>>4
            const int cin16 = (4 * cc) & 15;           // byte within 16B chunk
            *(__half2*)(grow + ((chnk ^ pxo) << 4) + cin16) = hp;
        }
    }
    __syncthreads();   // G complete

    // --- 3) main loop over 9 taps, double-buffered weights (r14 scheme) ---
    const int jbase = (wid & 1) * 64;
    const int pbase = (wid >> 1) * 32;
    const int tt = lane >> 3, r = lane & 7;
    const uint32_t aoff = (uint32_t)(((tt & 1) * 8 + r) * 144 + (tt >> 1) * 16);
    const int br  = (tt >> 1) * 8 + r;
    const int kcb = tt & 1;

    float acc[4][4][4];
#pragma unroll
    for (int a = 0; a < 4; a++)
#pragma unroll
        for (int b = 0; b < 4; b++)
#pragma unroll
            for (int c = 0; c < 4; c++) acc[a][b][c] = 0.0f;

    for (int t = 0; t < NTAPS; t++) {
        const uint32_t whi = sb + ((t & 1) ? SM_W1 : SM_W0);

        if (t == NTAPS - 1) cpasync_wait0(); else cpasync_wait1();
        __syncthreads();

        const int ky = t / 3, kx = t - ky * 3;
        const int pshift = pbase + ky * 64 + kx;

#pragma unroll
        for (int kq = 0; kq < 4; kq++) {
            const int k0 = kq * 16;
            uint32_t ah[4][4];
#pragma unroll
            for (int mt = 0; mt < 4; mt++) {
                uint32_t abase = (uint32_t)((jbase + mt * 16) * 144 + k0 * 2) + aoff;
                ldsm_x4(ah[mt][0], ah[mt][1], ah[mt][2], ah[mt][3], whi + abase);
            }
#pragma unroll
            for (int nt = 0; nt < 2; nt++) {
                const int P  = pshift + nt * 16 + br;
                const int kc = (k0 >> 3) + kcb;
                const uint32_t gb = (uint32_t)P * 128 + (uint32_t)((kc ^ (P & 7)) << 4);
                uint32_t bh[4];
                ldsm_x4(bh[0], bh[1], bh[2], bh[3], sb + SM_G + gb);
#pragma unroll
                for (int mt = 0; mt < 4; mt++) {
#pragma unroll
                    for (int sub = 0; sub < 2; sub++) {
                        mma16816(acc[mt][nt * 2 + sub], ah[mt],
                                 bh[2 * sub], bh[2 * sub + 1]);
                    }
                }
            }
        }

        // prefetch tap t+2 into the buffer just consumed
        if (t + 2 <= NTAPS - 1) {
            __syncthreads();
            const unsigned char* src = wsrc + (size_t)(t + 2) * WBLK;
#pragma unroll
            for (int c = 0; c < 5; c++) {
                int chunk = c * 256 + tid;
                if (chunk < 1152) cpasync16(whi + chunk * 16, src + chunk * 16);
            }
            cpasync_commit();
        }
    }

    // --- 4) epilogue: bias + float2 stores ---
    const float* sbias = (const float*)(smem + SM_BIAS);
#pragma unroll
    for (int mt = 0; mt < 4; mt++) {
        const int j0 = jbase + mt * 16 + (lane >> 2);
        const float b0 = sbias[j0];
        const float b1 = sbias[j0 + 8];
#pragma unroll
        for (int q = 0; q < 4; q++) {
            const int pos = pbase + q * 8 + 2 * (lane & 3);
            const int x = pos & 63;
            const int y = y0 + (pos >> 6);
            if (x < WO) {
                float2 v0 = make_float2(acc[mt][q][0] + b0, acc[mt][q][1] + b0);
                float2 v1 = make_float2(acc[mt][q][2] + b1, acc[mt][q][3] + b1);
                *(float2*)(out + (((size_t)eb * COUT + j0)     * HO + y) * WO + x) = v0;
                *(float2*)(out + (((size_t)eb * COUT + j0 + 8) * HO + y) * WO + x) = v1;
            }
        }
    }
}

// ---------------- launch ----------------
extern "C" void kernel_launch(void* const* d_in, const int* in_sizes, int n_in,
                              void* d_out, int out_size)
{
    const float* feat = (const float*)d_in[0];  // (E, B, C_in, H, W)
    const float* wgt  = (const float*)d_in[1];  // (E, C_in, C_out, 3, 3)
    const float* bias = (const float*)d_in[2];  // (E, C_out)
    float*       out  = (float*)d_out;          // (E, B, C_out, 62, 62)

    cudaFuncSetAttribute(conv_hmma_kernel,
                         cudaFuncAttributeMaxDynamicSharedMemorySize, SM_TOTAL);

    const int total = E * NTAPS * COUT * CIN;
    prep_weights_kernel<<<(total + 255) / 256, 256>>>(wgt);

    dim3 grid(HO / 2, E * Bn);  // (31, 128)
    conv_hmma_kernel<<<grid, 256, SM_TOTAL>>>(feat, bias, out);
}